// round 4
// baseline (speedup 1.0000x reference)
#include <cuda_runtime.h>

// ---------------- problem constants ----------------
#define SEQ     256
#define BATCH   128
#define HID     256
#define NLAYERS 12
#define NOUT    10

// scan kernel geometry: 128 blocks = 16 unit-groups x 8 batch-groups
#define NBLK         128
#define SCAN_THREADS 256
#define BB           16          // batch rows per block
#define UB           16          // hidden units per block (=> 64 gate cols)
#define XPAD         260         // padded row stride for x/h smem tiles

// smem layout (floats): W|U slice [512][64], x tile [16][260], h tile [16][260],
// gate partials A [16][64], gate partials B [16][64]
#define SM_W    0
#define SM_X    (512*64)
#define SM_H    (SM_X + BB*XPAD)
#define SM_GA   (SM_H + BB*XPAD)
#define SM_GB   (SM_GA + BB*64)
#define SM_TOT  (SM_GB + BB*64)   // 43136 floats = 172544 bytes

// ---------------- device scratch (no allocations allowed) ----------------
__device__ float    g_seq[2][(size_t)SEQ * BATCH * HID]; // ping-pong layer sequences
__device__ float    g_h[2][BATCH][HID];                  // ping-pong hidden state
__device__ float    g_c[BATCH][HID];                     // cell state (between layers)
__device__ unsigned g_count;                             // grid-barrier ticket counter

// ---------------- math helpers ----------------
__device__ __forceinline__ float sigf(float x) {
    return 1.0f / (1.0f + __expf(-x));
}
__device__ __forceinline__ float tanh_sig(float x) {
    // tanh(x) = 2*sigmoid(2x) - 1 ; saturates correctly at +-inf
    return fmaf(2.0f, sigf(2.0f * x), -1.0f);
}

// ---------------- init: zero h/c state, reset barrier counter ----------------
__global__ void init_state_kernel() {
    int i = blockIdx.x * blockDim.x + threadIdx.x;   // 64*512 = 32768 threads
    ((float*)g_h)[i]         = 0.0f;
    ((float*)g_h)[i + 32768] = 0.0f;
    ((float*)g_c)[i]         = 0.0f;
    if (i == 0) g_count = 0u;
}

// ---------------- embedding gather -> g_seq[0] laid out [s][b][e] ----------------
__global__ void embed_kernel(const int* __restrict__ x, const float* __restrict__ tab) {
    int idx = blockIdx.x * blockDim.x + threadIdx.x;     // over S*B*64 float4 chunks
    if (idx >= BATCH * SEQ * (HID / 4)) return;
    int e4 = idx & 63;            // float4 index within row
    int sb = idx >> 6;            // s*BATCH + b
    int b  = sb & (BATCH - 1);
    int s  = sb >> 7;
    int tok = x[b * SEQ + s];
    float4 v = *(const float4*)(tab + (size_t)tok * HID + e4 * 4);
    *(float4*)(&g_seq[0][(size_t)sb * HID + e4 * 4]) = v;
}

// ---------------- persistent fused LSTM layer scan ----------------
// Block (bx, by): hidden units [bx*16, bx*16+16), batch rows [by*16, by*16+16).
// Fused gates = x_t @ W + h_{t-1} @ U + b computed per step; grid barrier per step.
__global__ void __launch_bounds__(SCAN_THREADS, 1)
scan_kernel(int ping,
            const float* __restrict__ W,     // [256][1024]
            const float* __restrict__ U,     // [256][1024]
            const float* __restrict__ bias)  // [1024]
{
    extern __shared__ float sm[];
    float* Wsm  = sm + SM_W;
    float* xsm  = sm + SM_X;
    float* hsm  = sm + SM_H;
    float* gsmA = sm + SM_GA;
    float* gsmB = sm + SM_GB;

    const int tid = threadIdx.x;
    const int kh0 = blockIdx.x * UB;   // first hidden unit owned
    const int b0  = blockIdx.y * BB;   // first batch row owned

    // ---- one-time: load fused weight slice [512 rows][64 gate cols] ----
    // gate col jj = gate*16 + u  maps to full column gate*256 + kh0 + u
    for (int idx = tid; idx < 512 * 16; idx += SCAN_THREADS) {
        int k = idx >> 4;
        int c = idx & 15;
        int gate = c >> 2;
        int u4   = (c & 3) << 2;
        const float* src = (k < 256) ? (W + (size_t)k * 1024)
                                     : (U + (size_t)(k - 256) * 1024);
        float4 v = *(const float4*)(src + gate * 256 + kh0 + u4);
        *(float4*)(Wsm + k * 64 + gate * 16 + u4) = v;
    }

    // ---- gate-phase mapping: thread <-> (batch row, hidden unit), c in register ----
    const int gr = tid >> 4;          // 0..15 (local batch row)
    const int gu = tid & 15;          // 0..15 (local hidden unit)
    const int hb = b0 + gr;
    const int hu = kh0 + gu;
    float creg = g_c[hb][hu];
    const float bi = bias[hu];
    const float bf = bias[256 + hu];
    const float bg = bias[512 + hu];
    const float bo = bias[768 + hu];

    // ---- matmul mapping: warps 0-3 do x@W half (K=256), warps 4-7 do h@U half ----
    const int half = tid >> 7;                       // 0 or 1
    const int lt   = tid & 127;
    const int r0   = (lt >> 4) << 1;                 // rows r0, r0+1
    const int jq   = lt & 15;                        // cols jq*4 .. jq*4+3
    const float* wcol = Wsm + (half ? 256 * 64 : 0) + jq * 4;
    float* gout = (half ? gsmB : gsmA) + jq * 4;

    const float* xin  = g_seq[ping];
    float*       yout = g_seq[ping ^ 1];

    __syncthreads();

    for (int t = 0; t < SEQ; ++t) {
        // ---- stage x_t and h_{t-1} tiles into smem ----
        {
            const float* xrow = xin + ((size_t)t * BATCH + b0) * HID;
            const float* hrow = &g_h[t & 1][b0][0];
            for (int idx = tid; idx < BB * 64; idx += SCAN_THREADS) {
                int r  = idx >> 6;
                int c4 = (idx & 63) << 2;
                *(float4*)(xsm + r * XPAD + c4) = *(const float4*)(xrow + r * HID + c4);
                // h buffer is rewritten by other SMs every other step -> bypass L1
                *(float4*)(hsm + r * XPAD + c4) = __ldcg((const float4*)(hrow + r * HID + c4));
            }
        }
        __syncthreads();

        // ---- half-K matmul: 2 rows x 4 cols per thread ----
        {
            const float* ar0 = (half ? hsm : xsm) + r0 * XPAD;
            const float* ar1 = ar0 + XPAD;
            float a00 = 0.f, a01 = 0.f, a02 = 0.f, a03 = 0.f;
            float a10 = 0.f, a11 = 0.f, a12 = 0.f, a13 = 0.f;
            #pragma unroll 16
            for (int k = 0; k < 256; ++k) {
                float v0 = ar0[k];
                float v1 = ar1[k];
                float4 w = *(const float4*)(wcol + k * 64);
                a00 = fmaf(v0, w.x, a00);
                a01 = fmaf(v0, w.y, a01);
                a02 = fmaf(v0, w.z, a02);
                a03 = fmaf(v0, w.w, a03);
                a10 = fmaf(v1, w.x, a10);
                a11 = fmaf(v1, w.y, a11);
                a12 = fmaf(v1, w.z, a12);
                a13 = fmaf(v1, w.w, a13);
            }
            float4* o0 = (float4*)(gout + r0 * 64);
            float4* o1 = (float4*)(gout + (r0 + 1) * 64);
            *o0 = make_float4(a00, a01, a02, a03);
            *o1 = make_float4(a10, a11, a12, a13);
        }
        __syncthreads();

        // ---- gate nonlinearity + state update (c stays in register) ----
        {
            const int base = gr * 64 + gu;
            float gi = gsmA[base]      + gsmB[base]      + bi;
            float gf = gsmA[base + 16] + gsmB[base + 16] + bf;
            float gg = gsmA[base + 32] + gsmB[base + 32] + bg;
            float go = gsmA[base + 48] + gsmB[base + 48] + bo;
            float ct = sigf(gf) * creg + sigf(gi) * tanh_sig(gg);
            float hv = sigf(go) * tanh_sig(ct);
            creg = ct;
            __stcg(&g_h[(t + 1) & 1][hb][hu], hv);           // broadcast state (L2)
            yout[((size_t)t * BATCH + hb) * HID + hu] = hv;  // layer output sequence
        }
        __threadfence();   // make this thread's h store gpu-visible before arriving

        // ---- grid barrier: monotonic ticket counter, self-aligning ----
        __syncthreads();
        if (tid == 0) {
            unsigned base   = atomicAdd(&g_count, 1u);
            unsigned target = (base / NBLK + 1u) * NBLK;
            while (*(volatile unsigned*)&g_count < target) { }
            __threadfence();
        }
        __syncthreads();
    }

    g_c[hb][hu] = creg;   // thread state across layer launches
}

// ---------------- final FC: out[b][o] = h_final[b] . fcW[:,o] + fcb[o] ----------------
__global__ void fc_kernel(const float* __restrict__ fcW,
                          const float* __restrict__ fcb,
                          float* __restrict__ out)
{
    int idx = blockIdx.x * blockDim.x + threadIdx.x;
    if (idx >= BATCH * NOUT) return;
    int b = idx / NOUT;
    int o = idx - b * NOUT;
    float acc = fcb[o];
    const float* hrow = &g_h[0][b][0];   // after an even number of steps, h is in buf 0
    #pragma unroll 8
    for (int k = 0; k < HID; ++k)
        acc = fmaf(hrow[k], fcW[k * NOUT + o], acc);
    out[idx] = acc;
}

// ---------------- launch ----------------
extern "C" void kernel_launch(void* const* d_in, const int* in_sizes, int n_in,
                              void* d_out, int out_size)
{
    const int*   x   = (const int*)  d_in[0];
    const float* tab = (const float*)d_in[1];
    const float* W0  = (const float*)d_in[2];
    const float* U0  = (const float*)d_in[3];
    const float* b0  = (const float*)d_in[4];
    const float* Ws  = (const float*)d_in[5];
    const float* Us  = (const float*)d_in[6];
    const float* bs  = (const float*)d_in[7];
    const float* fcW = (const float*)d_in[8];
    const float* fcb = (const float*)d_in[9];
    float* out = (float*)d_out;

    cudaFuncSetAttribute(scan_kernel,
                         cudaFuncAttributeMaxDynamicSharedMemorySize,
                         SM_TOT * (int)sizeof(float));

    // state init (also resets barrier counter -> deterministic per replay)
    init_state_kernel<<<64, 512>>>();

    // embedding gather into g_seq[0]
    embed_kernel<<<(BATCH * SEQ * (HID / 4) + 255) / 256, 256>>>(x, tab);

    // 12 LSTM layers; layer 0 own weights, layers 1..11 shared weights
    for (int l = 0; l < NLAYERS; ++l) {
        scan_kernel<<<dim3(16, 8), SCAN_THREADS, SM_TOT * (int)sizeof(float)>>>(
            l & 1,
            l ? Ws : W0,
            l ? Us : U0,
            l ? bs : b0);
    }

    // final projection
    fc_kernel<<<(BATCH * NOUT + 255) / 256, 256>>>(fcW, fcb, out);

    (void)in_sizes; (void)n_in; (void)out_size;
}

// round 5
// speedup vs baseline: 1.2435x; 1.2435x over previous
#include <cuda_runtime.h>

// ---------------- problem constants ----------------
#define SEQ     256
#define BATCH   128
#define HID     256
#define NLAYERS 12
#define NOUT    10

// scan kernel geometry: 128 blocks = 16 unit-groups x 8 batch-groups
#define NBLK         128
#define SCAN_THREADS 256
#define BB           16          // batch rows per block
#define UB           16          // hidden units per block (=> 64 gate cols)
#define XPAD         258         // x/h tile row pitch (conflict-free row groups)
#define GPAD         66          // partial-buffer row pitch

// smem layout (float offsets)
#define SM_W    0                        // fused W|U slice [512][64]
#define SM_X    (SM_W + 512*64)          // x tile  [16][258]
#define SM_H    (SM_X + BB*XPAD)         // h tile  [16][258]
#define SM_G    (SM_H + BB*XPAD)         // 8 partial tiles [16][66]
#define SM_TOT  (SM_G + 8*BB*GPAD)       // 49472 floats = 197888 bytes

typedef unsigned long long ull;

// ---------------- device scratch (no allocations allowed) ----------------
__device__ float    g_seq[2][(size_t)SEQ * BATCH * HID]; // ping-pong layer sequences
__device__ float    g_h[2][BATCH][HID];                  // ping-pong hidden state
__device__ float    g_c[BATCH][HID];                     // cell state (persists across layers)
__device__ unsigned g_count;                             // grid-barrier ticket counter

// ---------------- packed f32x2 helpers ----------------
__device__ __forceinline__ ull fma2(ull a, ull b, ull c) {
    ull d;
    asm("fma.rn.f32x2 %0, %1, %2, %3;" : "=l"(d) : "l"(a), "l"(b), "l"(c));
    return d;
}
__device__ __forceinline__ ull pack2(float v) {
    ull d;
    asm("mov.b64 %0, {%1, %1};" : "=l"(d) : "f"(v));
    return d;
}

// ---------------- math helpers ----------------
__device__ __forceinline__ float sigf(float x) {
    return 1.0f / (1.0f + __expf(-x));
}
__device__ __forceinline__ float tanh_sig(float x) {
    return fmaf(2.0f, sigf(2.0f * x), -1.0f);   // tanh(x) = 2*sigmoid(2x) - 1
}

// ---------------- init: zero h/c state, reset barrier counter ----------------
__global__ void init_state_kernel() {
    int i = blockIdx.x * blockDim.x + threadIdx.x;   // 32768 threads
    ((float*)g_h)[i]         = 0.0f;
    ((float*)g_h)[i + 32768] = 0.0f;
    ((float*)g_c)[i]         = 0.0f;
    if (i == 0) g_count = 0u;
}

// ---------------- embedding gather -> g_seq[0] laid out [s][b][e] ----------------
__global__ void embed_kernel(const int* __restrict__ x, const float* __restrict__ tab) {
    int idx = blockIdx.x * blockDim.x + threadIdx.x;     // over S*B*64 float4 chunks
    if (idx >= BATCH * SEQ * (HID / 4)) return;
    int e4 = idx & 63;
    int sb = idx >> 6;            // s*BATCH + b
    int b  = sb & (BATCH - 1);
    int s  = sb >> 7;
    int tok = x[b * SEQ + s];
    float4 v = *(const float4*)(tab + (size_t)tok * HID + e4 * 4);
    *(float4*)(&g_seq[0][(size_t)sb * HID + e4 * 4]) = v;
}

// ---------------- persistent fused LSTM layer scan ----------------
// Block (bx, by): hidden units [bx*16,+16), batch rows [by*16,+16).
// 8 warps, warp w owns K chunk [w*64, w*64+64) of the fused K=512 (x|h),
// computing a full 16x64 gate-partial tile with R4xC8 f32x2 register blocking.
__global__ void __launch_bounds__(SCAN_THREADS, 1)
scan_kernel(int ping,
            const float* __restrict__ W,     // [256][1024]
            const float* __restrict__ U,     // [256][1024]
            const float* __restrict__ bias)  // [1024]
{
    extern __shared__ float sm[];
    float* Wsm = sm + SM_W;
    float* xsm = sm + SM_X;
    float* hsm = sm + SM_H;
    float* gsm = sm + SM_G;

    const int tid = threadIdx.x;
    const int kh0 = blockIdx.x * UB;   // first hidden unit owned
    const int b0  = blockIdx.y * BB;   // first batch row owned

    // ---- one-time: load fused weight slice [512 rows][64 gate cols] ----
    // gate col = gate*16 + u  maps to full column gate*256 + kh0 + u
    for (int idx = tid; idx < 512 * 16; idx += SCAN_THREADS) {
        int k = idx >> 4;
        int c = idx & 15;
        int gate = c >> 2;
        int u4   = (c & 3) << 2;
        const float* src = (k < 256) ? (W + (size_t)k * 1024)
                                     : (U + (size_t)(k - 256) * 1024);
        float4 v = *(const float4*)(src + gate * 256 + kh0 + u4);
        *(float4*)(Wsm + k * 64 + gate * 16 + u4) = v;
    }

    // ---- gate-phase mapping: thread <-> (batch row, hidden unit) ----
    const int gr = tid >> 4;          // local batch row 0..15
    const int gu = tid & 15;          // local hidden unit 0..15
    const int hb = b0 + gr;
    const int hu = kh0 + gu;
    float creg = g_c[hb][hu];
    const float bi = bias[hu];
    const float bf = bias[256 + hu];
    const float bg = bias[512 + hu];
    const float bo = bias[768 + hu];

    // ---- matmul mapping: warp w -> K chunk, lane -> (row group, col group) ----
    const int w  = tid >> 5;           // 0..7
    const int ln = tid & 31;
    const int rg = ln >> 3;            // rows 4*rg .. 4*rg+3
    const int cg = ln & 7;             // col pairs {2*cg + 16*j}, j=0..3
    const float* Apane = (w < 4) ? xsm : hsm;
    const int    k0    = (w & 3) * 64;
    const float* wbase = Wsm + (size_t)(w * 64) * 64 + 2 * cg;
    float*       gout  = gsm + w * (BB * GPAD);

    const float* xin  = g_seq[ping];
    float*       yout = g_seq[ping ^ 1];

    // ---- prologue: stage x_0 and h_0 ----
    {
        const float* xrow = xin + (size_t)b0 * HID;
        const float* hrow = &g_h[0][b0][0];
        for (int idx = tid; idx < BB * (HID / 2); idx += SCAN_THREADS) {
            int r  = idx >> 7;
            int c2 = idx & 127;
            ((float2*)(xsm + r * XPAD))[c2] = ((const float2*)(xrow + r * HID))[c2];
            ((float2*)(hsm + r * XPAD))[c2] = __ldcg(((const float2*)(hrow + r * HID)) + c2);
        }
    }
    __syncthreads();

    for (int t = 0; t < SEQ; ++t) {
        // ---- K-chunk matmul: 4 rows x 8 cols per thread, f32x2 packed FMA ----
        {
            const float* a0 = Apane + (4 * rg + 0) * XPAD + k0;
            const float* a1 = a0 + XPAD;
            const float* a2 = a1 + XPAD;
            const float* a3 = a2 + XPAD;
            ull acc[4][4];
            #pragma unroll
            for (int r = 0; r < 4; ++r)
                #pragma unroll
                for (int j = 0; j < 4; ++j)
                    acc[r][j] = 0ull;

            #pragma unroll 8
            for (int kk = 0; kk < 64; ++kk) {
                const float* wr = wbase + kk * 64;
                ull w0 = *(const ull*)(wr);
                ull w1 = *(const ull*)(wr + 16);
                ull w2 = *(const ull*)(wr + 32);
                ull w3 = *(const ull*)(wr + 48);
                ull v;
                v = pack2(a0[kk]);
                acc[0][0] = fma2(v, w0, acc[0][0]);
                acc[0][1] = fma2(v, w1, acc[0][1]);
                acc[0][2] = fma2(v, w2, acc[0][2]);
                acc[0][3] = fma2(v, w3, acc[0][3]);
                v = pack2(a1[kk]);
                acc[1][0] = fma2(v, w0, acc[1][0]);
                acc[1][1] = fma2(v, w1, acc[1][1]);
                acc[1][2] = fma2(v, w2, acc[1][2]);
                acc[1][3] = fma2(v, w3, acc[1][3]);
                v = pack2(a2[kk]);
                acc[2][0] = fma2(v, w0, acc[2][0]);
                acc[2][1] = fma2(v, w1, acc[2][1]);
                acc[2][2] = fma2(v, w2, acc[2][2]);
                acc[2][3] = fma2(v, w3, acc[2][3]);
                v = pack2(a3[kk]);
                acc[3][0] = fma2(v, w0, acc[3][0]);
                acc[3][1] = fma2(v, w1, acc[3][1]);
                acc[3][2] = fma2(v, w2, acc[3][2]);
                acc[3][3] = fma2(v, w3, acc[3][3]);
            }

            #pragma unroll
            for (int r = 0; r < 4; ++r) {
                float* orow = gout + (4 * rg + r) * GPAD + 2 * cg;
                #pragma unroll
                for (int j = 0; j < 4; ++j)
                    *(ull*)(orow + 16 * j) = acc[r][j];
            }
        }
        __syncthreads();

        // ---- gate nonlinearity + state update (c stays in register) ----
        {
            float s0 = bi, s1 = bf, s2 = bg, s3 = bo;
            #pragma unroll
            for (int ww = 0; ww < 8; ++ww) {
                const float* gp = gsm + ww * (BB * GPAD) + gr * GPAD;
                s0 += gp[gu];
                s1 += gp[16 + gu];
                s2 += gp[32 + gu];
                s3 += gp[48 + gu];
            }
            float ct = sigf(s1) * creg + sigf(s0) * tanh_sig(s2);
            float hv = sigf(s3) * tanh_sig(ct);
            creg = ct;
            __stcg(&g_h[(t + 1) & 1][hb][hu], hv);           // broadcast state (L2)
            yout[((size_t)t * BATCH + hb) * HID + hu] = hv;  // layer output sequence
        }

        if (t < SEQ - 1) {
            __threadfence();                 // make h stores gpu-visible
            __syncthreads();                 // all block stores done; partials consumed

            unsigned target = 0;
            if (tid == 0) {                  // arrive early...
                unsigned base = atomicAdd(&g_count, 1u);
                target = (base / NBLK + 1u) * NBLK;
            }

            // ...then overlap: stage x_{t+1} while other blocks finish / we'd spin
            {
                const float* xrow = xin + ((size_t)(t + 1) * BATCH + b0) * HID;
                for (int idx = tid; idx < BB * (HID / 2); idx += SCAN_THREADS) {
                    int r  = idx >> 7;
                    int c2 = idx & 127;
                    ((float2*)(xsm + r * XPAD))[c2] =
                        ((const float2*)(xrow + r * HID))[c2];
                }
            }

            if (tid == 0) {
                while (*(volatile unsigned*)&g_count < target) { }
                __threadfence();
            }
            __syncthreads();                 // barrier released for whole block

            // stage h_{t+1} (produced by other SMs -> bypass L1)
            {
                const float* hrow = &g_h[(t + 1) & 1][b0][0];
                for (int idx = tid; idx < BB * (HID / 2); idx += SCAN_THREADS) {
                    int r  = idx >> 7;
                    int c2 = idx & 127;
                    ((float2*)(hsm + r * XPAD))[c2] =
                        __ldcg(((const float2*)(hrow + r * HID)) + c2);
                }
            }
            __syncthreads();
        }
    }

    g_c[hb][hu] = creg;   // thread cell state across layer launches
}

// ---------------- final FC: out[b][o] = h_final[b] . fcW[:,o] + fcb[o] ----------------
__global__ void fc_kernel(const float* __restrict__ fcW,
                          const float* __restrict__ fcb,
                          float* __restrict__ out)
{
    int idx = blockIdx.x * blockDim.x + threadIdx.x;
    if (idx >= BATCH * NOUT) return;
    int b = idx / NOUT;
    int o = idx - b * NOUT;
    float acc = fcb[o];
    const float* hrow = &g_h[0][b][0];   // after 256 steps, final h lands in buf 0
    #pragma unroll 8
    for (int k = 0; k < HID; ++k)
        acc = fmaf(hrow[k], fcW[k * NOUT + o], acc);
    out[idx] = acc;
}

// ---------------- launch ----------------
extern "C" void kernel_launch(void* const* d_in, const int* in_sizes, int n_in,
                              void* d_out, int out_size)
{
    const int*   x   = (const int*)  d_in[0];
    const float* tab = (const float*)d_in[1];
    const float* W0  = (const float*)d_in[2];
    const float* U0  = (const float*)d_in[3];
    const float* b0  = (const float*)d_in[4];
    const float* Ws  = (const float*)d_in[5];
    const float* Us  = (const float*)d_in[6];
    const float* bs  = (const float*)d_in[7];
    const float* fcW = (const float*)d_in[8];
    const float* fcb = (const float*)d_in[9];
    float* out = (float*)d_out;

    cudaFuncSetAttribute(scan_kernel,
                         cudaFuncAttributeMaxDynamicSharedMemorySize,
                         SM_TOT * (int)sizeof(float));

    init_state_kernel<<<64, 512>>>();   // also resets barrier counter per replay

    embed_kernel<<<(BATCH * SEQ * (HID / 4) + 255) / 256, 256>>>(x, tab);

    for (int l = 0; l < NLAYERS; ++l) {
        scan_kernel<<<dim3(16, 8), SCAN_THREADS, SM_TOT * (int)sizeof(float)>>>(
            l & 1,
            l ? Ws : W0,
            l ? Us : U0,
            l ? bs : b0);
    }

    fc_kernel<<<(BATCH * NOUT + 255) / 256, 256>>>(fcW, fcb, out);

    (void)in_sizes; (void)n_in; (void)out_size;
}

// round 6
// speedup vs baseline: 1.3034x; 1.0481x over previous
#include <cuda_runtime.h>

// ---------------- problem constants ----------------
#define SEQ     256
#define BATCH   128
#define HID     256
#define NLAYERS 12
#define NOUT    10

// scan kernel geometry: 128 blocks = 16 unit-groups x 8 batch-groups
#define NBLK         128
#define SCAN_THREADS 256
#define BB           16          // batch rows per block
#define UB           16          // hidden units per block (=> 64 gate cols)
#define XPAD         258         // x/h tile row pitch (conflict-free row groups)
#define GPAD         66          // partial-buffer row pitch

// smem layout (float offsets)
#define SM_W    0                        // fused W|U slice [512][64]
#define SM_X    (SM_W + 512*64)          // x tile  [16][258]
#define SM_H    (SM_X + BB*XPAD)         // h tile  [16][258]
#define SM_G    (SM_H + BB*XPAD)         // 8 partial tiles [16][66]
#define SM_TOT  (SM_G + 8*BB*GPAD)       // 49472 floats = 197888 bytes

typedef unsigned long long ull;

// ---------------- device scratch (no allocations allowed) ----------------
__device__ float    g_seq[2][(size_t)SEQ * BATCH * HID]; // ping-pong layer sequences
__device__ float    g_h[2][BATCH][HID];                  // ping-pong hidden state
__device__ float    g_c[BATCH][HID];                     // cell state (persists across layers)
__device__ unsigned g_count;                             // grid-barrier ticket counter

// ---------------- packed f32x2 helpers ----------------
__device__ __forceinline__ ull fma2(ull a, ull b, ull c) {
    ull d;
    asm("fma.rn.f32x2 %0, %1, %2, %3;" : "=l"(d) : "l"(a), "l"(b), "l"(c));
    return d;
}
__device__ __forceinline__ ull pack2(float v) {
    ull d;
    asm("mov.b64 %0, {%1, %1};" : "=l"(d) : "f"(v));
    return d;
}

// ---------------- math helpers ----------------
__device__ __forceinline__ float sigf(float x) {
    return 1.0f / (1.0f + __expf(-x));
}
__device__ __forceinline__ float tanh_sig(float x) {
    return fmaf(2.0f, sigf(2.0f * x), -1.0f);   // tanh(x) = 2*sigmoid(2x) - 1
}

// ---------------- init: zero h/c state, reset barrier counter ----------------
__global__ void init_state_kernel() {
    int i = blockIdx.x * blockDim.x + threadIdx.x;   // 32768 threads
    ((float*)g_h)[i]         = 0.0f;
    ((float*)g_h)[i + 32768] = 0.0f;
    ((float*)g_c)[i]         = 0.0f;
    if (i == 0) g_count = 0u;
}

// ---------------- embedding gather -> g_seq[0] laid out [s][b][e] ----------------
__global__ void embed_kernel(const int* __restrict__ x, const float* __restrict__ tab) {
    int idx = blockIdx.x * blockDim.x + threadIdx.x;     // over S*B*64 float4 chunks
    if (idx >= BATCH * SEQ * (HID / 4)) return;
    int e4 = idx & 63;
    int sb = idx >> 6;            // s*BATCH + b
    int b  = sb & (BATCH - 1);
    int s  = sb >> 7;
    int tok = x[b * SEQ + s];
    float4 v = *(const float4*)(tab + (size_t)tok * HID + e4 * 4);
    *(float4*)(&g_seq[0][(size_t)sb * HID + e4 * 4]) = v;
}

// ---------------- persistent fused LSTM layer scan ----------------
// Block (bx, by): hidden units [bx*16,+16), batch rows [by*16,+16).
// 8 warps, warp w owns K chunk [w*64, w*64+64) of the fused K=512 (x|h),
// computing a full 16x64 gate-partial tile with R4xC8 f32x2 register blocking.
__global__ void __launch_bounds__(SCAN_THREADS, 1)
scan_kernel(int ping,
            const float* __restrict__ W,     // [256][1024]
            const float* __restrict__ U,     // [256][1024]
            const float* __restrict__ bias)  // [1024]
{
    extern __shared__ float sm[];
    float* Wsm = sm + SM_W;
    float* xsm = sm + SM_X;
    float* hsm = sm + SM_H;
    float* gsm = sm + SM_G;

    const int tid = threadIdx.x;
    const int kh0 = blockIdx.x * UB;   // first hidden unit owned
    const int b0  = blockIdx.y * BB;   // first batch row owned

    // ---- one-time: load fused weight slice [512 rows][64 gate cols] ----
    // gate col = gate*16 + u  maps to full column gate*256 + kh0 + u
    for (int idx = tid; idx < 512 * 16; idx += SCAN_THREADS) {
        int k = idx >> 4;
        int c = idx & 15;
        int gate = c >> 2;
        int u4   = (c & 3) << 2;
        const float* src = (k < 256) ? (W + (size_t)k * 1024)
                                     : (U + (size_t)(k - 256) * 1024);
        float4 v = *(const float4*)(src + gate * 256 + kh0 + u4);
        *(float4*)(Wsm + k * 64 + gate * 16 + u4) = v;
    }

    // ---- gate-phase mapping: thread <-> (batch row, hidden unit) ----
    const int gr = tid >> 4;          // local batch row 0..15
    const int gu = tid & 15;          // local hidden unit 0..15
    const int hb = b0 + gr;
    const int hu = kh0 + gu;
    float creg = g_c[hb][hu];
    const float bi = bias[hu];
    const float bf = bias[256 + hu];
    const float bg = bias[512 + hu];
    const float bo = bias[768 + hu];

    // ---- matmul mapping: warp w -> K chunk, lane -> (row group, col group) ----
    const int w  = tid >> 5;           // 0..7
    const int ln = tid & 31;
    const int rg = ln >> 3;            // rows 4*rg .. 4*rg+3
    const int cg = ln & 7;             // col pairs {2*cg + 16*j}, j=0..3
    const float* Apane = (w < 4) ? xsm : hsm;
    const int    k0    = (w & 3) * 64;
    const float* wbase = Wsm + (size_t)(w * 64) * 64 + 2 * cg;
    float*       gout  = gsm + w * (BB * GPAD);

    const float* xin  = g_seq[ping];
    float*       yout = g_seq[ping ^ 1];

    // ---- prologue: stage x_0 and h_0 ----
    {
        const float* xrow = xin + (size_t)b0 * HID;
        const float* hrow = &g_h[0][b0][0];
        for (int idx = tid; idx < BB * (HID / 2); idx += SCAN_THREADS) {
            int r  = idx >> 7;
            int c2 = idx & 127;
            ((float2*)(xsm + r * XPAD))[c2] = ((const float2*)(xrow + r * HID))[c2];
            ((float2*)(hsm + r * XPAD))[c2] = __ldcg(((const float2*)(hrow + r * HID)) + c2);
        }
    }
    __syncthreads();

    for (int t = 0; t < SEQ; ++t) {
        // ---- K-chunk matmul: 4 rows x 8 cols per thread, f32x2 packed FMA ----
        {
            const float* a0 = Apane + (4 * rg + 0) * XPAD + k0;
            const float* a1 = a0 + XPAD;
            const float* a2 = a1 + XPAD;
            const float* a3 = a2 + XPAD;
            ull acc[4][4];
            #pragma unroll
            for (int r = 0; r < 4; ++r)
                #pragma unroll
                for (int j = 0; j < 4; ++j)
                    acc[r][j] = 0ull;

            #pragma unroll 8
            for (int kk = 0; kk < 64; ++kk) {
                const float* wr = wbase + kk * 64;
                ull w0 = *(const ull*)(wr);
                ull w1 = *(const ull*)(wr + 16);
                ull w2 = *(const ull*)(wr + 32);
                ull w3 = *(const ull*)(wr + 48);
                ull v;
                v = pack2(a0[kk]);
                acc[0][0] = fma2(v, w0, acc[0][0]);
                acc[0][1] = fma2(v, w1, acc[0][1]);
                acc[0][2] = fma2(v, w2, acc[0][2]);
                acc[0][3] = fma2(v, w3, acc[0][3]);
                v = pack2(a1[kk]);
                acc[1][0] = fma2(v, w0, acc[1][0]);
                acc[1][1] = fma2(v, w1, acc[1][1]);
                acc[1][2] = fma2(v, w2, acc[1][2]);
                acc[1][3] = fma2(v, w3, acc[1][3]);
                v = pack2(a2[kk]);
                acc[2][0] = fma2(v, w0, acc[2][0]);
                acc[2][1] = fma2(v, w1, acc[2][1]);
                acc[2][2] = fma2(v, w2, acc[2][2]);
                acc[2][3] = fma2(v, w3, acc[2][3]);
                v = pack2(a3[kk]);
                acc[3][0] = fma2(v, w0, acc[3][0]);
                acc[3][1] = fma2(v, w1, acc[3][1]);
                acc[3][2] = fma2(v, w2, acc[3][2]);
                acc[3][3] = fma2(v, w3, acc[3][3]);
            }

            #pragma unroll
            for (int r = 0; r < 4; ++r) {
                float* orow = gout + (4 * rg + r) * GPAD + 2 * cg;
                #pragma unroll
                for (int j = 0; j < 4; ++j)
                    *(ull*)(orow + 16 * j) = acc[r][j];
            }
        }
        __syncthreads();

        // ---- gate nonlinearity + state update (c stays in register) ----
        {
            float s0 = bi, s1 = bf, s2 = bg, s3 = bo;
            #pragma unroll
            for (int ww = 0; ww < 8; ++ww) {
                const float* gp = gsm + ww * (BB * GPAD) + gr * GPAD;
                s0 += gp[gu];
                s1 += gp[16 + gu];
                s2 += gp[32 + gu];
                s3 += gp[48 + gu];
            }
            float ct = sigf(s1) * creg + sigf(s0) * tanh_sig(s2);
            float hv = sigf(s3) * tanh_sig(ct);
            creg = ct;
            __stcg(&g_h[(t + 1) & 1][hb][hu], hv);           // broadcast state (L2)
            yout[((size_t)t * BATCH + hb) * HID + hu] = hv;  // layer output sequence
        }

        if (t < SEQ - 1) {
            __threadfence();                 // make h stores gpu-visible
            __syncthreads();                 // all block stores done; partials consumed

            unsigned target = 0;
            if (tid == 0) {                  // arrive early...
                unsigned base = atomicAdd(&g_count, 1u);
                target = (base / NBLK + 1u) * NBLK;
            }

            // ...then overlap: stage x_{t+1} while other blocks finish / we'd spin
            {
                const float* xrow = xin + ((size_t)(t + 1) * BATCH + b0) * HID;
                for (int idx = tid; idx < BB * (HID / 2); idx += SCAN_THREADS) {
                    int r  = idx >> 7;
                    int c2 = idx & 127;
                    ((float2*)(xsm + r * XPAD))[c2] =
                        ((const float2*)(xrow + r * HID))[c2];
                }
            }

            if (tid == 0) {
                while (*(volatile unsigned*)&g_count < target) { }
                __threadfence();
            }
            __syncthreads();                 // barrier released for whole block

            // stage h_{t+1} (produced by other SMs -> bypass L1)
            {
                const float* hrow = &g_h[(t + 1) & 1][b0][0];
                for (int idx = tid; idx < BB * (HID / 2); idx += SCAN_THREADS) {
                    int r  = idx >> 7;
                    int c2 = idx & 127;
                    ((float2*)(hsm + r * XPAD))[c2] =
                        __ldcg(((const float2*)(hrow + r * HID)) + c2);
                }
            }
            __syncthreads();
        }
    }

    g_c[hb][hu] = creg;   // thread cell state across layer launches
}

// ---------------- final FC: out[b][o] = h_final[b] . fcW[:,o] + fcb[o] ----------------
__global__ void fc_kernel(const float* __restrict__ fcW,
                          const float* __restrict__ fcb,
                          float* __restrict__ out)
{
    int idx = blockIdx.x * blockDim.x + threadIdx.x;
    if (idx >= BATCH * NOUT) return;
    int b = idx / NOUT;
    int o = idx - b * NOUT;
    float acc = fcb[o];
    const float* hrow = &g_h[0][b][0];   // after 256 steps, final h lands in buf 0
    #pragma unroll 8
    for (int k = 0; k < HID; ++k)
        acc = fmaf(hrow[k], fcW[k * NOUT + o], acc);
    out[idx] = acc;
}

// ---------------- launch ----------------
extern "C" void kernel_launch(void* const* d_in, const int* in_sizes, int n_in,
                              void* d_out, int out_size)
{
    const int*   x   = (const int*)  d_in[0];
    const float* tab = (const float*)d_in[1];
    const float* W0  = (const float*)d_in[2];
    const float* U0  = (const float*)d_in[3];
    const float* b0  = (const float*)d_in[4];
    const float* Ws  = (const float*)d_in[5];
    const float* Us  = (const float*)d_in[6];
    const float* bs  = (const float*)d_in[7];
    const float* fcW = (const float*)d_in[8];
    const float* fcb = (const float*)d_in[9];
    float* out = (float*)d_out;

    cudaFuncSetAttribute(scan_kernel,
                         cudaFuncAttributeMaxDynamicSharedMemorySize,
                         SM_TOT * (int)sizeof(float));

    init_state_kernel<<<64, 512>>>();   // also resets barrier counter per replay

    embed_kernel<<<(BATCH * SEQ * (HID / 4) + 255) / 256, 256>>>(x, tab);

    for (int l = 0; l < NLAYERS; ++l) {
        scan_kernel<<<dim3(16, 8), SCAN_THREADS, SM_TOT * (int)sizeof(float)>>>(
            l & 1,
            l ? Ws : W0,
            l ? Us : U0,
            l ? bs : b0);
    }

    fc_kernel<<<(BATCH * NOUT + 255) / 256, 256>>>(fcW, fcb, out);

    (void)in_sizes; (void)n_in; (void)out_size;
}

// round 7
// speedup vs baseline: 1.3072x; 1.0029x over previous
#include <cuda_runtime.h>

// ---------------- problem constants ----------------
#define SEQ     256
#define BATCH   128
#define HID     256
#define NLAYERS 12
#define NOUT    10

// scan kernel geometry: 128 blocks = 16 unit-groups x 8 batch-groups
#define NBLK         128
#define SCAN_THREADS 256
#define BB           16          // batch rows per block
#define UB           16          // hidden units per block (=> 64 gate cols)
#define XPAD         258         // x/h tile row pitch (conflict-free row groups)
#define GPAD         66          // partial-buffer row pitch

// smem layout (float offsets)
#define SM_W    0                        // fused W|U slice [512][64]
#define SM_X    (SM_W + 512*64)          // x tile  [16][258]
#define SM_H    (SM_X + BB*XPAD)         // h tile  [16][258]
#define SM_G    (SM_H + BB*XPAD)         // 8 partial tiles [16][66]
#define SM_TOT  (SM_G + 8*BB*GPAD)       // 49472 floats = 197888 bytes

typedef unsigned long long ull;

// ---------------- device scratch (no allocations allowed) ----------------
__device__ float    g_seq[2][(size_t)SEQ * BATCH * HID]; // ping-pong layer sequences
__device__ float    g_h[2][BATCH][HID];                  // ping-pong hidden state
__device__ float    g_c[BATCH][HID];                     // cell state (persists across layers)
__device__ unsigned g_count;                             // grid-barrier ticket counter

// ---------------- packed f32x2 helpers ----------------
__device__ __forceinline__ ull fma2(ull a, ull b, ull c) {
    ull d;
    asm("fma.rn.f32x2 %0, %1, %2, %3;" : "=l"(d) : "l"(a), "l"(b), "l"(c));
    return d;
}
__device__ __forceinline__ ull pack2(float v) {
    ull d;
    asm("mov.b64 %0, {%1, %1};" : "=l"(d) : "f"(v));
    return d;
}

// ---------------- math helpers ----------------
__device__ __forceinline__ float sigf(float x) {
    return 1.0f / (1.0f + __expf(-x));
}
__device__ __forceinline__ float tanh_sig(float x) {
    return fmaf(2.0f, sigf(2.0f * x), -1.0f);   // tanh(x) = 2*sigmoid(2x) - 1
}

// ---------------- init: zero h/c state, reset barrier counter ----------------
__global__ void init_state_kernel() {
    int i = blockIdx.x * blockDim.x + threadIdx.x;   // 32768 threads
    ((float*)g_h)[i]         = 0.0f;
    ((float*)g_h)[i + 32768] = 0.0f;
    ((float*)g_c)[i]         = 0.0f;
    if (i == 0) g_count = 0u;
}

// ---------------- embedding gather -> g_seq[0] laid out [s][b][e] ----------------
__global__ void embed_kernel(const int* __restrict__ x, const float* __restrict__ tab) {
    int idx = blockIdx.x * blockDim.x + threadIdx.x;     // over S*B*64 float4 chunks
    if (idx >= BATCH * SEQ * (HID / 4)) return;
    int e4 = idx & 63;
    int sb = idx >> 6;            // s*BATCH + b
    int b  = sb & (BATCH - 1);
    int s  = sb >> 7;
    int tok = x[b * SEQ + s];
    float4 v = *(const float4*)(tab + (size_t)tok * HID + e4 * 4);
    *(float4*)(&g_seq[0][(size_t)sb * HID + e4 * 4]) = v;
}

// ---------------- persistent fused LSTM layer scan ----------------
// Block (bx, by): hidden units [bx*16,+16), batch rows [by*16,+16).
// 8 warps, warp w owns K chunk [w*64, w*64+64) of the fused K=512 (x|h),
// computing a full 16x64 gate-partial tile with R4xC8 f32x2 register blocking.
__global__ void __launch_bounds__(SCAN_THREADS, 1)
scan_kernel(int ping,
            const float* __restrict__ W,     // [256][1024]
            const float* __restrict__ U,     // [256][1024]
            const float* __restrict__ bias)  // [1024]
{
    extern __shared__ float sm[];
    float* Wsm = sm + SM_W;
    float* xsm = sm + SM_X;
    float* hsm = sm + SM_H;
    float* gsm = sm + SM_G;

    const int tid = threadIdx.x;
    const int kh0 = blockIdx.x * UB;   // first hidden unit owned
    const int b0  = blockIdx.y * BB;   // first batch row owned

    // ---- one-time: load fused weight slice [512 rows][64 gate cols] ----
    // gate col = gate*16 + u  maps to full column gate*256 + kh0 + u
    for (int idx = tid; idx < 512 * 16; idx += SCAN_THREADS) {
        int k = idx >> 4;
        int c = idx & 15;
        int gate = c >> 2;
        int u4   = (c & 3) << 2;
        const float* src = (k < 256) ? (W + (size_t)k * 1024)
                                     : (U + (size_t)(k - 256) * 1024);
        float4 v = *(const float4*)(src + gate * 256 + kh0 + u4);
        *(float4*)(Wsm + k * 64 + gate * 16 + u4) = v;
    }

    // ---- gate-phase mapping: thread <-> (batch row, hidden unit) ----
    const int gr = tid >> 4;          // local batch row 0..15
    const int gu = tid & 15;          // local hidden unit 0..15
    const int hb = b0 + gr;
    const int hu = kh0 + gu;
    float creg = g_c[hb][hu];
    const float bi = bias[hu];
    const float bf = bias[256 + hu];
    const float bg = bias[512 + hu];
    const float bo = bias[768 + hu];

    // ---- matmul mapping: warp w -> K chunk, lane -> (row group, col group) ----
    const int w  = tid >> 5;           // 0..7
    const int ln = tid & 31;
    const int rg = ln >> 3;            // rows 4*rg .. 4*rg+3
    const int cg = ln & 7;             // col pairs {2*cg + 16*j}, j=0..3
    const float* Apane = (w < 4) ? xsm : hsm;
    const int    k0    = (w & 3) * 64;
    const float* wbase = Wsm + (size_t)(w * 64) * 64 + 2 * cg;
    float*       gout  = gsm + w * (BB * GPAD);

    const float* xin  = g_seq[ping];
    float*       yout = g_seq[ping ^ 1];

    // ---- prologue: stage x_0 and h_0 ----
    {
        const float* xrow = xin + (size_t)b0 * HID;
        const float* hrow = &g_h[0][b0][0];
        for (int idx = tid; idx < BB * (HID / 2); idx += SCAN_THREADS) {
            int r  = idx >> 7;
            int c2 = idx & 127;
            ((float2*)(xsm + r * XPAD))[c2] = ((const float2*)(xrow + r * HID))[c2];
            ((float2*)(hsm + r * XPAD))[c2] = __ldcg(((const float2*)(hrow + r * HID)) + c2);
        }
    }
    __syncthreads();

    for (int t = 0; t < SEQ; ++t) {
        // ---- K-chunk matmul: 4 rows x 8 cols per thread, f32x2 packed FMA ----
        {
            const float* a0 = Apane + (4 * rg + 0) * XPAD + k0;
            const float* a1 = a0 + XPAD;
            const float* a2 = a1 + XPAD;
            const float* a3 = a2 + XPAD;
            ull acc[4][4];
            #pragma unroll
            for (int r = 0; r < 4; ++r)
                #pragma unroll
                for (int j = 0; j < 4; ++j)
                    acc[r][j] = 0ull;

            #pragma unroll 8
            for (int kk = 0; kk < 64; ++kk) {
                const float* wr = wbase + kk * 64;
                ull w0 = *(const ull*)(wr);
                ull w1 = *(const ull*)(wr + 16);
                ull w2 = *(const ull*)(wr + 32);
                ull w3 = *(const ull*)(wr + 48);
                ull v;
                v = pack2(a0[kk]);
                acc[0][0] = fma2(v, w0, acc[0][0]);
                acc[0][1] = fma2(v, w1, acc[0][1]);
                acc[0][2] = fma2(v, w2, acc[0][2]);
                acc[0][3] = fma2(v, w3, acc[0][3]);
                v = pack2(a1[kk]);
                acc[1][0] = fma2(v, w0, acc[1][0]);
                acc[1][1] = fma2(v, w1, acc[1][1]);
                acc[1][2] = fma2(v, w2, acc[1][2]);
                acc[1][3] = fma2(v, w3, acc[1][3]);
                v = pack2(a2[kk]);
                acc[2][0] = fma2(v, w0, acc[2][0]);
                acc[2][1] = fma2(v, w1, acc[2][1]);
                acc[2][2] = fma2(v, w2, acc[2][2]);
                acc[2][3] = fma2(v, w3, acc[2][3]);
                v = pack2(a3[kk]);
                acc[3][0] = fma2(v, w0, acc[3][0]);
                acc[3][1] = fma2(v, w1, acc[3][1]);
                acc[3][2] = fma2(v, w2, acc[3][2]);
                acc[3][3] = fma2(v, w3, acc[3][3]);
            }

            #pragma unroll
            for (int r = 0; r < 4; ++r) {
                float* orow = gout + (4 * rg + r) * GPAD + 2 * cg;
                #pragma unroll
                for (int j = 0; j < 4; ++j)
                    *(ull*)(orow + 16 * j) = acc[r][j];
            }
        }
        __syncthreads();

        // ---- gate nonlinearity + state update (c stays in register) ----
        {
            float s0 = bi, s1 = bf, s2 = bg, s3 = bo;
            #pragma unroll
            for (int ww = 0; ww < 8; ++ww) {
                const float* gp = gsm + ww * (BB * GPAD) + gr * GPAD;
                s0 += gp[gu];
                s1 += gp[16 + gu];
                s2 += gp[32 + gu];
                s3 += gp[48 + gu];
            }
            float ct = sigf(s1) * creg + sigf(s0) * tanh_sig(s2);
            float hv = sigf(s3) * tanh_sig(ct);
            creg = ct;
            __stcg(&g_h[(t + 1) & 1][hb][hu], hv);           // broadcast state (L2)
            yout[((size_t)t * BATCH + hb) * HID + hu] = hv;  // layer output sequence
        }

        if (t < SEQ - 1) {
            __threadfence();                 // make h stores gpu-visible
            __syncthreads();                 // all block stores done; partials consumed

            unsigned target = 0;
            if (tid == 0) {                  // arrive early...
                unsigned base = atomicAdd(&g_count, 1u);
                target = (base / NBLK + 1u) * NBLK;
            }

            // ...then overlap: stage x_{t+1} while other blocks finish / we'd spin
            {
                const float* xrow = xin + ((size_t)(t + 1) * BATCH + b0) * HID;
                for (int idx = tid; idx < BB * (HID / 2); idx += SCAN_THREADS) {
                    int r  = idx >> 7;
                    int c2 = idx & 127;
                    ((float2*)(xsm + r * XPAD))[c2] =
                        ((const float2*)(xrow + r * HID))[c2];
                }
            }

            if (tid == 0) {
                while (*(volatile unsigned*)&g_count < target) { }
                __threadfence();
            }
            __syncthreads();                 // barrier released for whole block

            // stage h_{t+1} (produced by other SMs -> bypass L1)
            {
                const float* hrow = &g_h[(t + 1) & 1][b0][0];
                for (int idx = tid; idx < BB * (HID / 2); idx += SCAN_THREADS) {
                    int r  = idx >> 7;
                    int c2 = idx & 127;
                    ((float2*)(hsm + r * XPAD))[c2] =
                        __ldcg(((const float2*)(hrow + r * HID)) + c2);
                }
            }
            __syncthreads();
        }
    }

    g_c[hb][hu] = creg;   // thread cell state across layer launches
}

// ---------------- final FC: out[b][o] = h_final[b] . fcW[:,o] + fcb[o] ----------------
__global__ void fc_kernel(const float* __restrict__ fcW,
                          const float* __restrict__ fcb,
                          float* __restrict__ out)
{
    int idx = blockIdx.x * blockDim.x + threadIdx.x;
    if (idx >= BATCH * NOUT) return;
    int b = idx / NOUT;
    int o = idx - b * NOUT;
    float acc = fcb[o];
    const float* hrow = &g_h[0][b][0];   // after 256 steps, final h lands in buf 0
    #pragma unroll 8
    for (int k = 0; k < HID; ++k)
        acc = fmaf(hrow[k], fcW[k * NOUT + o], acc);
    out[idx] = acc;
}

// ---------------- launch ----------------
extern "C" void kernel_launch(void* const* d_in, const int* in_sizes, int n_in,
                              void* d_out, int out_size)
{
    const int*   x   = (const int*)  d_in[0];
    const float* tab = (const float*)d_in[1];
    const float* W0  = (const float*)d_in[2];
    const float* U0  = (const float*)d_in[3];
    const float* b0  = (const float*)d_in[4];
    const float* Ws  = (const float*)d_in[5];
    const float* Us  = (const float*)d_in[6];
    const float* bs  = (const float*)d_in[7];
    const float* fcW = (const float*)d_in[8];
    const float* fcb = (const float*)d_in[9];
    float* out = (float*)d_out;

    cudaFuncSetAttribute(scan_kernel,
                         cudaFuncAttributeMaxDynamicSharedMemorySize,
                         SM_TOT * (int)sizeof(float));

    init_state_kernel<<<64, 512>>>();   // also resets barrier counter per replay

    embed_kernel<<<(BATCH * SEQ * (HID / 4) + 255) / 256, 256>>>(x, tab);

    for (int l = 0; l < NLAYERS; ++l) {
        scan_kernel<<<dim3(16, 8), SCAN_THREADS, SM_TOT * (int)sizeof(float)>>>(
            l & 1,
            l ? Ws : W0,
            l ? Us : U0,
            l ? bs : b0);
    }

    fc_kernel<<<(BATCH * NOUT + 255) / 256, 256>>>(fcW, fcb, out);

    (void)in_sizes; (void)n_in; (void)out_size;
}

// round 8
// speedup vs baseline: 1.3205x; 1.0102x over previous
#include <cuda_runtime.h>

// ---------------- problem constants ----------------
#define SEQ     256
#define BATCH   128
#define HID     256
#define NLAYERS 12
#define NOUT    10

// scan geometry: 128 blocks = 16 unit-groups x 8 batch-groups, persistent
#define NBLK         128
#define SCAN_THREADS 256
#define BB           16            // batch rows per block
#define UB           16            // hidden units per block (=> 64 gate cols)
#define APITCH       514           // duplicated x/h tile row pitch (floats)
#define GPAD         66            // partial-buffer row pitch

// smem layout (float offsets)
#define SM_W    0                          // fused W|U slice [512][64]
#define SM_X    (SM_W + 512*64)            // x tile dup  [16][514]
#define SM_H    (SM_X + BB*APITCH)         // h tile dup  [16][514]
#define SM_G    (SM_H + BB*APITCH)         // 8 partial tiles [16][66]
#define SM_TOT  (SM_G + 8*BB*GPAD)         // 57664 floats = 230656 bytes

typedef unsigned long long ull;

// ---------------- device scratch (no allocations allowed) ----------------
__device__ float    g_seq[2][(size_t)SEQ * BATCH * HID]; // ping-pong layer sequences
__device__ float    g_h[2][BATCH][HID];                  // ping-pong hidden state
__device__ unsigned g_count;                             // grid-barrier ticket counter

// ---------------- packed f32x2 + barrier helpers ----------------
__device__ __forceinline__ ull fma2(ull a, ull b, ull c) {
    ull d;
    asm("fma.rn.f32x2 %0, %1, %2, %3;" : "=l"(d) : "l"(a), "l"(b), "l"(c));
    return d;
}
__device__ __forceinline__ ull pack2(float v) {
    ull d;
    asm("mov.b64 %0, {%1, %1};" : "=l"(d) : "f"(v));
    return d;
}
__device__ __forceinline__ void bar_arrive(unsigned* p) {
    asm volatile("red.release.gpu.add.u32 [%0], %1;" :: "l"(p), "r"(1u) : "memory");
}
__device__ __forceinline__ unsigned ld_acq(const unsigned* p) {
    unsigned v;
    asm volatile("ld.acquire.gpu.u32 %0, [%1];" : "=r"(v) : "l"(p) : "memory");
    return v;
}

// ---------------- math helpers ----------------
__device__ __forceinline__ float sigf(float x) {
    return 1.0f / (1.0f + __expf(-x));
}
__device__ __forceinline__ float tanh_sig(float x) {
    return fmaf(2.0f, sigf(2.0f * x), -1.0f);   // tanh(x) = 2*sigmoid(2x) - 1
}

// ---------------- init: reset barrier counter (deterministic per replay) ----------------
__global__ void init_state_kernel() {
    if (threadIdx.x == 0 && blockIdx.x == 0) g_count = 0u;
}

// ---------------- embedding gather -> g_seq[0] laid out [s][b][e] ----------------
__global__ void embed_kernel(const int* __restrict__ x, const float* __restrict__ tab) {
    int idx = blockIdx.x * blockDim.x + threadIdx.x;     // over S*B*64 float4 chunks
    if (idx >= BATCH * SEQ * (HID / 4)) return;
    int e4 = idx & 63;
    int sb = idx >> 6;            // s*BATCH + b
    int b  = sb & (BATCH - 1);
    int s  = sb >> 7;
    int tok = x[b * SEQ + s];
    float4 v = *(const float4*)(tab + (size_t)tok * HID + e4 * 4);
    *(float4*)(&g_seq[0][(size_t)sb * HID + e4 * 4]) = v;
}

// ---------------- block helpers (all-thread cooperative) ----------------
// Load fused weight slice [512 rows][64 gate cols] for this block's unit group.
__device__ __forceinline__ void load_wslice(float* Wsm, const float* W,
                                            const float* U, int kh0) {
    for (int idx = threadIdx.x; idx < 512 * 16; idx += SCAN_THREADS) {
        int k = idx >> 4;
        int c = idx & 15;
        int gate = c >> 2;
        int u4   = (c & 3) << 2;
        const float* src = (k < 256) ? (W + (size_t)k * 1024)
                                     : (U + (size_t)(k - 256) * 1024);
        float4 v = *(const float4*)(src + gate * 256 + kh0 + u4);
        *(float4*)(Wsm + k * 64 + gate * 16 + u4) = v;
    }
}

// Stage a 16x256 tile into duplicated {v,v} layout (pitch APITCH).
template <bool BYPASS>
__device__ __forceinline__ void stage_dup(float* dst, const float* src) {
    for (int idx = threadIdx.x; idx < BB * (HID / 2); idx += SCAN_THREADS) {
        int r  = idx >> 7;
        int c2 = idx & 127;
        float2 v = BYPASS ? __ldcg(((const float2*)(src + r * HID)) + c2)
                          : ((const float2*)(src + r * HID))[c2];
        ull* d = (ull*)(dst + r * APITCH) + 2 * c2;
        d[0] = pack2(v.x);
        d[1] = pack2(v.y);
    }
}

__device__ __forceinline__ void stage_zero(float* dst) {
    for (int idx = threadIdx.x; idx < BB * (HID / 2); idx += SCAN_THREADS) {
        int r  = idx >> 7;
        int c2 = idx & 127;
        ull* d = (ull*)(dst + r * APITCH) + 2 * c2;
        d[0] = 0ull;
        d[1] = 0ull;
    }
}

// ---------------- persistent 12-layer LSTM scan ----------------
// Block (bx, by): hidden units [bx*16,+16), batch rows [by*16,+16).
// 8 warps, warp w owns K chunk [w*64,+64) of fused K=512 (x|h),
// computing the 16x64 gate-partial tile with R4xC8 f32x2 register blocking.
__global__ void __launch_bounds__(SCAN_THREADS, 1)
scan_all_kernel(const float* __restrict__ W0, const float* __restrict__ U0,
                const float* __restrict__ b0,
                const float* __restrict__ Ws, const float* __restrict__ Us,
                const float* __restrict__ bs)
{
    extern __shared__ float sm[];
    float* Wsm = sm + SM_W;
    float* xsm = sm + SM_X;
    float* hsm = sm + SM_H;
    float* gsm = sm + SM_G;

    const int tid = threadIdx.x;
    const int kh0 = blockIdx.x * UB;   // first hidden unit owned
    const int b0r = blockIdx.y * BB;   // first batch row owned

    // ---- gate-phase mapping ----
    const int gr = tid >> 4;          // local batch row 0..15
    const int gu = tid & 15;          // local hidden unit 0..15
    const int hb = b0r + gr;
    const int hu = kh0 + gu;
    float creg = 0.0f;                // cell state lives in a register for all 12 layers
    float bi = b0[hu];
    float bf = b0[256 + hu];
    float bg = b0[512 + hu];
    float bo = b0[768 + hu];

    // ---- matmul mapping: warp -> K chunk, lane -> (row group, col group) ----
    const int w  = tid >> 5;           // 0..7
    const int ln = tid & 31;
    const int rg = ln >> 3;            // rows 4*rg .. 4*rg+3
    const int cg = ln & 7;             // col pairs {2*cg + 16*j}
    const ull* Apane = (const ull*)((w < 4) ? xsm : hsm);
    const int  koff  = (w & 3) * 64;   // ull offset of warp's K chunk within pane row
    const ull* wbase = (const ull*)(Wsm + (size_t)(w * 64) * 64) + cg;
    float*     gout  = gsm + w * (BB * GPAD);

    const float* xin  = g_seq[0];
    float*       yout = g_seq[1];

    // ---- prologue: layer-0 weights, x_0, h_0 = 0 ----
    load_wslice(Wsm, W0, U0, kh0);
    stage_dup<false>(xsm, xin + (size_t)b0r * HID);
    stage_zero(hsm);
    __syncthreads();

    unsigned barn = 0;                 // barriers completed so far (same in all blocks)

    for (int l = 0; l < NLAYERS; ++l) {
        for (int t = 0; t < SEQ; ++t) {
            // ---- K-chunk matmul: 4 rows x 8 cols per thread, f32x2 ----
            {
                const ull* a0 = Apane + (4 * rg + 0) * (APITCH / 2) + koff;
                const ull* a1 = a0 + (APITCH / 2);
                const ull* a2 = a1 + (APITCH / 2);
                const ull* a3 = a2 + (APITCH / 2);
                ull acc[4][4];
                #pragma unroll
                for (int r = 0; r < 4; ++r)
                    #pragma unroll
                    for (int j = 0; j < 4; ++j)
                        acc[r][j] = 0ull;

                #pragma unroll 8
                for (int kk = 0; kk < 64; ++kk) {
                    const ull* wr = wbase + kk * 32;
                    ull w0 = wr[0];
                    ull w1 = wr[8];
                    ull w2 = wr[16];
                    ull w3 = wr[24];
                    ull v;
                    v = a0[kk];
                    acc[0][0] = fma2(v, w0, acc[0][0]);
                    acc[0][1] = fma2(v, w1, acc[0][1]);
                    acc[0][2] = fma2(v, w2, acc[0][2]);
                    acc[0][3] = fma2(v, w3, acc[0][3]);
                    v = a1[kk];
                    acc[1][0] = fma2(v, w0, acc[1][0]);
                    acc[1][1] = fma2(v, w1, acc[1][1]);
                    acc[1][2] = fma2(v, w2, acc[1][2]);
                    acc[1][3] = fma2(v, w3, acc[1][3]);
                    v = a2[kk];
                    acc[2][0] = fma2(v, w0, acc[2][0]);
                    acc[2][1] = fma2(v, w1, acc[2][1]);
                    acc[2][2] = fma2(v, w2, acc[2][2]);
                    acc[2][3] = fma2(v, w3, acc[2][3]);
                    v = a3[kk];
                    acc[3][0] = fma2(v, w0, acc[3][0]);
                    acc[3][1] = fma2(v, w1, acc[3][1]);
                    acc[3][2] = fma2(v, w2, acc[3][2]);
                    acc[3][3] = fma2(v, w3, acc[3][3]);
                }

                #pragma unroll
                for (int r = 0; r < 4; ++r) {
                    float* orow = gout + (4 * rg + r) * GPAD + 2 * cg;
                    #pragma unroll
                    for (int j = 0; j < 4; ++j)
                        *(ull*)(orow + 16 * j) = acc[r][j];
                }
            }
            __syncthreads();

            // ---- gate nonlinearity + state update (c stays in register) ----
            {
                float s0 = bi, s1 = bf, s2 = bg, s3 = bo;
                #pragma unroll
                for (int ww = 0; ww < 8; ++ww) {
                    const float* gp = gsm + ww * (BB * GPAD) + gr * GPAD;
                    s0 += gp[gu];
                    s1 += gp[16 + gu];
                    s2 += gp[32 + gu];
                    s3 += gp[48 + gu];
                }
                float ct = sigf(s1) * creg + sigf(s0) * tanh_sig(s2);
                float hv = sigf(s3) * tanh_sig(ct);
                creg = ct;
                __stcg(&g_h[(t + 1) & 1][hb][hu], hv);           // broadcast state (L2)
                yout[((size_t)t * BATCH + hb) * HID + hu] = hv;  // layer output sequence
            }

            if (l == NLAYERS - 1 && t == SEQ - 1) break;

            // ---- grid barrier (release/acquire), staging overlapped ----
            __syncthreads();                       // block's h stores + gsm reads done
            if (tid == 0) bar_arrive(&g_count);    // fire-and-forget release
            ++barn;
            const unsigned tgt = barn * NBLK;

            if (t < SEQ - 1) {
                // next step's x (no cross-block dependency)
                stage_dup<false>(xsm, xin + ((size_t)(t + 1) * BATCH + b0r) * HID);
            } else {
                // layer boundary: shared weights load only once (l==0 -> l==1)
                if (l == 0) {
                    load_wslice(Wsm, Ws, Us, kh0);
                    bi = bs[hu];
                    bf = bs[256 + hu];
                    bg = bs[512 + hu];
                    bo = bs[768 + hu];
                }
                // next layer's x_0 = this layer's output at t=0 (long since visible)
                stage_dup<false>(xsm, yout + (size_t)b0r * HID);
            }

            while (ld_acq(&g_count) < tgt) { }     // every thread acquires

            // h_{t+1} (produced by other SMs) -> duplicated smem pane
            stage_dup<true>(hsm, &g_h[(t + 1) & 1][b0r][0]);
            __syncthreads();
        }
        // swap sequence buffers for next layer
        const float* tx = xin;
        xin  = yout;
        yout = (float*)tx;
    }
}

// ---------------- final FC: out[b][o] = h_final[b] . fcW[:,o] + fcb[o] ----------------
__global__ void fc_kernel(const float* __restrict__ fcW,
                          const float* __restrict__ fcb,
                          float* __restrict__ out)
{
    int idx = blockIdx.x * blockDim.x + threadIdx.x;
    if (idx >= BATCH * NOUT) return;
    int b = idx / NOUT;
    int o = idx - b * NOUT;
    float acc = fcb[o];
    const float* hrow = &g_h[0][b][0];   // t=255 writes parity (255+1)&1 = buf 0
    #pragma unroll 8
    for (int k = 0; k < HID; ++k)
        acc = fmaf(hrow[k], fcW[k * NOUT + o], acc);
    out[idx] = acc;
}

// ---------------- launch ----------------
extern "C" void kernel_launch(void* const* d_in, const int* in_sizes, int n_in,
                              void* d_out, int out_size)
{
    const int*   x   = (const int*)  d_in[0];
    const float* tab = (const float*)d_in[1];
    const float* W0  = (const float*)d_in[2];
    const float* U0  = (const float*)d_in[3];
    const float* b0  = (const float*)d_in[4];
    const float* Ws  = (const float*)d_in[5];
    const float* Us  = (const float*)d_in[6];
    const float* bs  = (const float*)d_in[7];
    const float* fcW = (const float*)d_in[8];
    const float* fcb = (const float*)d_in[9];
    float* out = (float*)d_out;

    cudaFuncSetAttribute(scan_all_kernel,
                         cudaFuncAttributeMaxDynamicSharedMemorySize,
                         SM_TOT * (int)sizeof(float));

    init_state_kernel<<<1, 32>>>();     // reset barrier counter per replay

    embed_kernel<<<(BATCH * SEQ * (HID / 4) + 255) / 256, 256>>>(x, tab);

    scan_all_kernel<<<dim3(16, 8), SCAN_THREADS, SM_TOT * (int)sizeof(float)>>>(
        W0, U0, b0, Ws, Us, bs);

    fc_kernel<<<(BATCH * NOUT + 255) / 256, 256>>>(fcW, fcb, out);

    (void)in_sizes; (void)n_in; (void)out_size;
}